// round 14
// baseline (speedup 1.0000x reference)
#include <cuda_runtime.h>
#include <cuda_fp16.h>
#include <cstdint>

#define CIN   256
#define COUT  256
#define LEN   8192
#define KK    7
#define BATCH 4
#define NT    128    // l-tile
#define TLO   128    // l-tile of offsets kernel
#define NCHUNK 4     // i-chunks of 64 per k
#define NLT   (LEN / NT)   // 64 l-tiles

// ---------------- device scratch ----------------
__device__ int2   g_tidx[BATCH * KK * LEN];   // (x0c, x1c)
__device__ float2 g_tw[BATCH * KK * LEN];     // (wa, wb)
// weight tiles: t = (k*4+ic)*2+oh, each [128 o][64 i] fp16, SW128 pre-swizzled
__device__ __half g_wA[KK * NCHUNK * 2 * 8192];
// interp tiles: tile = ((b*7+k)*4+ic)*64+lt, each [128 l][64 i] fp16, SW128 pre-swizzled
__device__ __half g_I[(size_t)BATCH * KK * NCHUNK * NLT * 8192];

#define SWZ128(x)  ((x) ^ (((x) >> 3) & 0x70))
#define SLOT_BYTES 32768   // A 16K + B 16K
#define NSTAGE 3

// ---------------- PTX helpers (portable, sm_80-era) ----------------
__device__ __forceinline__ uint32_t smem_u32(const void* p) {
    uint32_t a;
    asm("{ .reg .u64 t; cvta.to.shared.u64 t, %1; cvt.u32.u64 %0, t; }" : "=r"(a) : "l"(p));
    return a;
}
__device__ __forceinline__ void cp16(uint32_t dst, const void* src) {
    asm volatile("cp.async.cg.shared.global [%0], [%1], 16;" :: "r"(dst), "l"(src));
}
__device__ __forceinline__ void ldsm4(uint32_t* r, uint32_t addr) {
    asm volatile("ldmatrix.sync.aligned.m8n8.x4.shared.b16 {%0,%1,%2,%3}, [%4];"
        : "=r"(r[0]), "=r"(r[1]), "=r"(r[2]), "=r"(r[3]) : "r"(addr));
}
__device__ __forceinline__ void mma16816(float* c, const uint32_t* a, const uint32_t* b) {
    asm volatile("mma.sync.aligned.m16n8k16.row.col.f32.f16.f16.f32 "
        "{%0,%1,%2,%3}, {%4,%5,%6,%7}, {%8,%9}, {%0,%1,%2,%3};"
        : "+f"(c[0]), "+f"(c[1]), "+f"(c[2]), "+f"(c[3])
        : "r"(a[0]), "r"(a[1]), "r"(a[2]), "r"(a[3]), "r"(b[0]), "r"(b[1]));
}
// pack two f32 -> f16x2 (rn); first src operand -> high half
__device__ __forceinline__ uint32_t cvt_f16x2(float lo, float hi) {
    uint32_t r;
    asm("cvt.rn.f16x2.f32 %0, %1, %2;" : "=r"(r) : "f"(hi), "f"(lo));
    return r;
}

// ---------- kernel 1: weight fp16 + pre-swizzle ----------
__global__ void wprep_kernel(const float* __restrict__ w) {
    int e = blockIdx.x * 256 + threadIdx.x;
    if (e >= KK * NCHUNK * 2 * 8192) return;
    int t  = e >> 13;
    int r  = e & 8191;
    int o  = r >> 6;
    int i  = r & 63;
    int oh = t & 1;
    int ic = (t >> 1) & 3;
    int k  = t >> 3;
    float v = w[((oh * 128 + o) * CIN + ic * 64 + i) * KK + k];
    uint32_t swz = SWZ128((uint32_t)(o * 128 + i * 2));
    g_wA[t * 8192 + (swz >> 1)] = __float2half(v);
}

// ---------- kernel 2: offset conv + interpolation tables ----------
__global__ __launch_bounds__(256, 1) void offsets_kernel(
    const float* __restrict__ x,
    const float* __restrict__ ow,
    const float* __restrict__ ob)
{
    extern __shared__ float sm[];
    float* xs  = sm;              // 256 * 136
    float* ows = sm + 256 * 136;  // 7 * 256 * 8

    int tid = threadIdx.x;
    int b   = blockIdx.y;
    int l0  = blockIdx.x * TLO;
    const float* xb = x + (size_t)b * CIN * LEN;

    for (int idx = tid; idx < 256 * 134; idx += 256) {
        int i = idx / 134;
        int c = idx - i * 134;
        int g = l0 - 3 + c;
        xs[i * 136 + c] = (g >= 0 && g < LEN) ? xb[i * LEN + g] : 0.0f;
    }
    for (int e = tid; e < KK * CIN * KK; e += 256) {
        int r  = e / 7;
        int kk = e - r * 7;
        ows[r * 8 + kk] = ow[e];
    }
    __syncthreads();

    int w    = tid >> 5;
    int lane = tid & 31;
    if (w < 7) {
        int k = w;
        float a0 = 0.f, a1 = 0.f, a2 = 0.f, a3 = 0.f;
        const float* xrow0 = xs + 4 * lane;
        const float* wrow  = ows + k * 256 * 8;
        #pragma unroll 4
        for (int i = 0; i < 256; i++) {
            const float4* xr = (const float4*)(xrow0 + i * 136);
            float4 A = xr[0], B4 = xr[1], C4 = xr[2];
            float xw[12] = {A.x, A.y, A.z, A.w, B4.x, B4.y, B4.z, B4.w,
                            C4.x, C4.y, C4.z, C4.w};
            const float4* wr = (const float4*)(wrow + i * 8);
            float4 W0 = wr[0], W1 = wr[1];
            float wv[7] = {W0.x, W0.y, W0.z, W0.w, W1.x, W1.y, W1.z};
            #pragma unroll
            for (int kk = 0; kk < 7; kk++) {
                a0 += wv[kk] * xw[0 + kk];
                a1 += wv[kk] * xw[1 + kk];
                a2 += wv[kk] * xw[2 + kk];
                a3 += wv[kk] * xw[3 + kk];
            }
        }
        float bk = ob[k];
        float accs[4] = {a0, a1, a2, a3};
        #pragma unroll
        for (int d = 0; d < 4; d++) {
            int lg = l0 + 4 * lane + d;
            float loc = (float)(lg + k) + accs[d] + bk;
            int ix0 = (int)floorf(loc);
            int i0c = min(max(ix0, 0), LEN - 1);
            int i1c = min(max(ix0 + 1, 0), LEN - 1);
            int o = (b * 7 + k) * LEN + lg;
            g_tidx[o] = make_int2(i0c, i1c);
            g_tw[o]   = make_float2((float)i1c - loc, loc - (float)i0c);
        }
    }
}

// ---------- kernel 3: interp gather -> pre-swizzled fp16 tiles ----------
// block = (lt, ic, b), 256 threads; thread: l = tid/2, i-half = (tid&1)*32.
// k-loop inside: x-slab for fixed (lt,ic) reused across the 7 k (L1-resident).
__global__ __launch_bounds__(256, 4) void interp_kernel(const float* __restrict__ x)
{
    int lt  = blockIdx.x;
    int ic  = blockIdx.y;
    int b   = blockIdx.z;
    int tid = threadIdx.x;
    int l   = tid >> 1;
    int ih  = (tid & 1) * 32;
    const float* xb = x + (size_t)b * CIN * LEN;

    #pragma unroll
    for (int k = 0; k < KK; k++) {
        int tix = (b * 7 + k) * LEN + lt * NT + l;
        int2   ii = g_tidx[tix];
        float2 wv = g_tw[tix];
        const float* p0 = xb + ii.x;
        const float* p1 = xb + ii.y;
        char* tile = (char*)(g_I + (size_t)(((b * 7 + k) * 4 + ic) * NLT + lt) * 8192);

        #pragma unroll
        for (int g = 0; g < 4; g++) {
            uint32_t hp[4];
            #pragma unroll
            for (int j = 0; j < 4; j++) {
                size_t i0 = (size_t)(ic * 64 + ih + g * 8 + j * 2) * LEN;
                float v0 = wv.x * p0[i0]       + wv.y * p1[i0];
                float v1 = wv.x * p0[i0 + LEN] + wv.y * p1[i0 + LEN];
                hp[j] = cvt_f16x2(v0, v1);
            }
            uint32_t so = SWZ128((uint32_t)(l * 128 + (ih + g * 8) * 2));
            *(uint4*)(tile + so) = make_uint4(hp[0], hp[1], hp[2], hp[3]);
        }
    }
}

// ---------- kernel 4: main GEMM, vanilla 3-stage cp.async pipeline ----------
// CTA: (lt, oh, b), 256 threads, 8 warps = 2(o) x 4(l), occ 2.
__global__ __launch_bounds__(256, 2) void main_kernel(
    const float* __restrict__ bias,
    float* __restrict__ out)
{
    extern __shared__ char smem[];
    uint32_t sb = smem_u32(smem);

    int tid  = threadIdx.x;
    int wid  = tid >> 5;
    int lane = tid & 31;
    int lt   = blockIdx.x;
    int oh   = blockIdx.y;
    int b    = blockIdx.z;
    int ow   = wid >> 2;
    int lw   = wid & 3;

    // stage issuer: stage s -> chunk s (k = s/4, ic = s%4), slot s%3
    auto issue = [&](int s) {
        if (s < KK * NCHUNK) {
            int k  = s >> 2;
            int ic = s & 3;
            uint32_t base = sb + (s % NSTAGE) * SLOT_BYTES;
            const char* srcA = (const char*)(g_wA + (size_t)((k * 4 + ic) * 2 + oh) * 8192);
            const char* srcB = (const char*)(g_I + (size_t)(((b * 7 + k) * 4 + ic) * NLT + lt) * 8192);
            #pragma unroll
            for (int q = 0; q < 4; q++)
                cp16(base + q * 4096 + tid * 16, srcA + q * 4096 + tid * 16);
            #pragma unroll
            for (int q = 0; q < 4; q++)
                cp16(base + 16384 + q * 4096 + tid * 16, srcB + q * 4096 + tid * 16);
        }
        asm volatile("cp.async.commit_group;" ::: "memory");
    };

    float c[4][4][4];
    #pragma unroll
    for (int ot = 0; ot < 4; ot++)
        #pragma unroll
        for (int nt = 0; nt < 4; nt++)
            #pragma unroll
            for (int r = 0; r < 4; r++) c[ot][nt][r] = 0.f;

    issue(0);
    issue(1);

    for (int cc = 0; cc < KK * NCHUNK; cc++) {
        asm volatile("cp.async.wait_group 1;" ::: "memory");   // stage cc ready
        __syncthreads();                                       // + slot (cc-1)%3 free
        issue(cc + 2);

        uint32_t aB = sb + (cc % NSTAGE) * SLOT_BYTES;
        uint32_t bB = aB + 16384;

        #pragma unroll
        for (int ks = 0; ks < 4; ks++) {
            uint32_t bf[4][2];
            #pragma unroll
            for (int np = 0; np < 2; np++) {
                int row = lw * 32 + np * 16 + ((lane >> 4) << 3) + (lane & 7);
                uint32_t off = SWZ128((uint32_t)(row * 128 + ks * 32 + ((lane >> 3) & 1) * 16));
                uint32_t r[4];
                ldsm4(r, bB + off);
                bf[np * 2][0]     = r[0]; bf[np * 2][1]     = r[1];
                bf[np * 2 + 1][0] = r[2]; bf[np * 2 + 1][1] = r[3];
            }
            #pragma unroll
            for (int ot = 0; ot < 4; ot++) {
                int row = ow * 64 + ot * 16 + (lane & 15);
                uint32_t off = SWZ128((uint32_t)(row * 128 + ks * 32 + (lane >> 4) * 16));
                uint32_t ah[4];
                ldsm4(ah, aB + off);
                #pragma unroll
                for (int nt = 0; nt < 4; nt++)
                    mma16816(c[ot][nt], ah, bf[nt]);
            }
        }
        __syncthreads();   // all warps done with slot before next refill cycle
    }

    // ---- epilogue: bias + store ----
    int og0 = oh * 128 + ow * 64;
    int l0  = lt * NT;
    #pragma unroll
    for (int ot = 0; ot < 4; ot++) {
        #pragma unroll
        for (int r2 = 0; r2 < 2; r2++) {
            int o = og0 + ot * 16 + (lane >> 2) + r2 * 8;
            float bj = bias[o];
            float* orow = out + ((size_t)(b * COUT + o)) * LEN + l0;
            #pragma unroll
            for (int nt = 0; nt < 4; nt++) {
                int lc = lw * 32 + nt * 8 + (lane & 3) * 2;
                *(float2*)(orow + lc) =
                    make_float2(c[ot][nt][r2 * 2] + bj, c[ot][nt][r2 * 2 + 1] + bj);
            }
        }
    }
}

// ---------------- launch ----------------
extern "C" void kernel_launch(void* const* d_in, const int* in_sizes, int n_in,
                              void* d_out, int out_size)
{
    const float* x        = (const float*)d_in[0];
    const float* weight   = (const float*)d_in[1];
    const float* bias     = (const float*)d_in[2];
    const float* offset_w = (const float*)d_in[3];
    const float* offset_b = (const float*)d_in[4];
    float* out = (float*)d_out;

    const int smem_off  = (256 * 136 + 7 * 256 * 8) * 4;   // 196608
    const int smem_main = NSTAGE * SLOT_BYTES;             // 98304

    cudaFuncSetAttribute(offsets_kernel, cudaFuncAttributeMaxDynamicSharedMemorySize, smem_off);
    cudaFuncSetAttribute(main_kernel,    cudaFuncAttributeMaxDynamicSharedMemorySize, smem_main);

    wprep_kernel<<<(KK * NCHUNK * 2 * 8192 + 255) / 256, 256>>>(weight);
    offsets_kernel<<<dim3(LEN / TLO, BATCH), 256, smem_off>>>(x, offset_w, offset_b);
    interp_kernel<<<dim3(NLT, NCHUNK, BATCH), 256>>>(x);
    main_kernel<<<dim3(NLT, 2, BATCH), 256, smem_main>>>(bias, out);
}

// round 15
// speedup vs baseline: 1.1133x; 1.1133x over previous
#include <cuda_runtime.h>
#include <cuda_fp16.h>
#include <cstdint>

#define CIN   256
#define COUT  256
#define LEN   8192
#define KK    7
#define BATCH 4
#define NT    128          // l-tile
#define NCHUNK 4           // i-chunks of 64 per k
#define NLT   (LEN / NT)   // 64 l-tiles
#define PCOLS 156          // prep slab columns
#define PORIG 11           // slab origin = l0 - PORIG

// ---------------- device scratch ----------------
// weight tiles: t = (k*4+ic)*2+oh, each [128 o][64 i] fp16, SW128 pre-swizzled
__device__ __half g_wA[KK * NCHUNK * 2 * 8192];
// interp tiles: tile = ((b*7+k)*4+ic)*64+lt, each [128 l][64 i] fp16, SW128 pre-swizzled
__device__ __half g_I[(size_t)BATCH * KK * NCHUNK * NLT * 8192];

#define SWZ128(x)  ((x) ^ (((x) >> 3) & 0x70))
#define SLOT_BYTES 32768   // A 16K + B 16K
#define NSTAGE 3

// ---------------- PTX helpers (portable, sm_80-era) ----------------
__device__ __forceinline__ uint32_t smem_u32(const void* p) {
    uint32_t a;
    asm("{ .reg .u64 t; cvta.to.shared.u64 t, %1; cvt.u32.u64 %0, t; }" : "=r"(a) : "l"(p));
    return a;
}
__device__ __forceinline__ void cp16(uint32_t dst, const void* src) {
    asm volatile("cp.async.cg.shared.global [%0], [%1], 16;" :: "r"(dst), "l"(src));
}
__device__ __forceinline__ void ldsm4(uint32_t* r, uint32_t addr) {
    asm volatile("ldmatrix.sync.aligned.m8n8.x4.shared.b16 {%0,%1,%2,%3}, [%4];"
        : "=r"(r[0]), "=r"(r[1]), "=r"(r[2]), "=r"(r[3]) : "r"(addr));
}
__device__ __forceinline__ void mma16816(float* c, const uint32_t* a, const uint32_t* b) {
    asm volatile("mma.sync.aligned.m16n8k16.row.col.f32.f16.f16.f32 "
        "{%0,%1,%2,%3}, {%4,%5,%6,%7}, {%8,%9}, {%0,%1,%2,%3};"
        : "+f"(c[0]), "+f"(c[1]), "+f"(c[2]), "+f"(c[3])
        : "r"(a[0]), "r"(a[1]), "r"(a[2]), "r"(a[3]), "r"(b[0]), "r"(b[1]));
}
// pack two f32 -> f16x2 (rn); first src operand -> high half
__device__ __forceinline__ uint32_t cvt_f16x2(float lo, float hi) {
    uint32_t r;
    asm("cvt.rn.f16x2.f32 %0, %1, %2;" : "=r"(r) : "f"(hi), "f"(lo));
    return r;
}

// ---------- kernel 1: weight fp16 + pre-swizzle ----------
__global__ void wprep_kernel(const float* __restrict__ w) {
    int e = blockIdx.x * 256 + threadIdx.x;
    if (e >= KK * NCHUNK * 2 * 8192) return;
    int t  = e >> 13;
    int r  = e & 8191;
    int o  = r >> 6;
    int i  = r & 63;
    int oh = t & 1;
    int ic = (t >> 1) & 3;
    int k  = t >> 3;
    float v = w[((oh * 128 + o) * CIN + ic * 64 + i) * KK + k];
    uint32_t swz = SWZ128((uint32_t)(o * 128 + i * 2));
    g_wA[t * 8192 + (swz >> 1)] = __float2half(v);
}

// ---------- kernel 2: fused prep: offset conv + tables + interp tiles ----------
// block = (lt, b), 512 threads, one smem x-slab serves conv AND gather.
// smem: xs[256][156] f32 (159744 B) + ows[7][256][8] (57344 B)
//       + wtab[7][128] float2 (7168 B) + btab[7][128] u16 (1792 B) = 226048 B.
__global__ __launch_bounds__(512, 1) void prep_kernel(
    const float* __restrict__ x,
    const float* __restrict__ ow,
    const float* __restrict__ ob)
{
    extern __shared__ float sm[];
    float*    xs   = sm;                          // [256][PCOLS]
    float*    ows  = sm + 256 * PCOLS;            // [7][256][8]
    float2*   wtab = (float2*)(ows + 7 * 256 * 8);// [7][128]
    uint16_t* btab = (uint16_t*)(wtab + 7 * 128); // [7][128]

    int tid = threadIdx.x;
    int lt  = blockIdx.x;
    int b   = blockIdx.y;
    int l0  = lt * NT;
    const float* xb = x + (size_t)b * CIN * LEN;

    // ---- phase 1: load slab (zero-pad OOB) + offset weights ----
    for (int idx = tid; idx < 256 * PCOLS; idx += 512) {
        int i = idx / PCOLS;
        int c = idx - i * PCOLS;
        int g = l0 - PORIG + c;
        xs[idx] = (g >= 0 && g < LEN) ? xb[i * LEN + g] : 0.0f;
    }
    for (int e = tid; e < KK * CIN * KK; e += 512) {
        int r  = e / 7;
        int kk = e - r * 7;
        ows[r * 8 + kk] = ow[e];
    }
    __syncthreads();

    // ---- phase 2: offset conv + interpolation tables (warps 0-6) ----
    int w    = tid >> 5;
    int lane = tid & 31;
    if (w < 7) {
        int k = w;
        float a0 = 0.f, a1 = 0.f, a2 = 0.f, a3 = 0.f;
        // conv window g = l0-3+4*lane+kk -> slab col 8+4*lane+kk (16B-aligned float4)
        const float* xrow0 = xs + 8 + 4 * lane;
        const float* wrow  = ows + k * 256 * 8;
        #pragma unroll 4
        for (int i = 0; i < 256; i++) {
            const float4* xr = (const float4*)(xrow0 + i * PCOLS);
            float4 A = xr[0], B4 = xr[1], C4 = xr[2];
            float xw[12] = {A.x, A.y, A.z, A.w, B4.x, B4.y, B4.z, B4.w,
                            C4.x, C4.y, C4.z, C4.w};
            const float4* wr = (const float4*)(wrow + i * 8);
            float4 W0 = wr[0], W1 = wr[1];
            float wv[7] = {W0.x, W0.y, W0.z, W0.w, W1.x, W1.y, W1.z};
            #pragma unroll
            for (int kk = 0; kk < 7; kk++) {
                a0 += wv[kk] * xw[0 + kk];
                a1 += wv[kk] * xw[1 + kk];
                a2 += wv[kk] * xw[2 + kk];
                a3 += wv[kk] * xw[3 + kk];
            }
        }
        float bk = ob[k];
        float accs[4] = {a0, a1, a2, a3};
        #pragma unroll
        for (int d = 0; d < 4; d++) {
            int l  = 4 * lane + d;
            int lg = l0 + l;
            float loc = (float)(lg + k) + accs[d] + bk;
            int ix0 = (int)floorf(loc);
            int i0c = min(max(ix0, 0), LEN - 1);
            int i1c = min(max(ix0 + 1, 0), LEN - 1);
            if (i1c == i0c) {
                // both endpoints clamp to same index -> wa+wb = 0 -> value 0
                wtab[k * 128 + l] = make_float2(0.f, 0.f);
                btab[k * 128 + l] = 0;
            } else {
                float wa = (float)i1c - loc;
                float wb = loc - (float)i0c;
                int col = i0c - l0 + PORIG;            // slab column of x0c
                col = min(max(col, 0), PCOLS - 2);     // impossible-tail guard
                wtab[k * 128 + l] = make_float2(wa, wb);
                btab[k * 128 + l] = (uint16_t)col;
            }
        }
    }
    __syncthreads();

    // ---- phase 3: interp tiles from slab (all 16 warps) ----
    // thread: l = tid&127 (warp = 32 consecutive l -> conflict-free LDS), ic = tid>>7
    int l  = tid & 127;
    int ic = tid >> 7;
    #pragma unroll
    for (int k = 0; k < KK; k++) {
        float2 wv = wtab[k * 128 + l];
        int col   = btab[k * 128 + l];
        const float* row = xs + col;
        char* tile = (char*)(g_I + (size_t)(((b * 7 + k) * 4 + ic) * NLT + lt) * 8192);
        int ibase = ic * 64;
        #pragma unroll
        for (int g = 0; g < 8; g++) {
            uint32_t hp[4];
            #pragma unroll
            for (int j = 0; j < 4; j++) {
                int i = ibase + g * 8 + j * 2;
                float v0 = wv.x * row[i * PCOLS]           + wv.y * row[i * PCOLS + 1];
                float v1 = wv.x * row[(i + 1) * PCOLS]     + wv.y * row[(i + 1) * PCOLS + 1];
                hp[j] = cvt_f16x2(v0, v1);
            }
            uint32_t so = SWZ128((uint32_t)(l * 128 + g * 16));
            *(uint4*)(tile + so) = make_uint4(hp[0], hp[1], hp[2], hp[3]);
        }
    }
}

// ---------- kernel 3: main GEMM, vanilla 3-stage cp.async pipeline ----------
// CTA: (lt, oh, b), 256 threads, 8 warps = 2(o) x 4(l), occ 2.
__global__ __launch_bounds__(256, 2) void main_kernel(
    const float* __restrict__ bias,
    float* __restrict__ out)
{
    extern __shared__ char smem[];
    uint32_t sb = smem_u32(smem);

    int tid  = threadIdx.x;
    int wid  = tid >> 5;
    int lane = tid & 31;
    int lt   = blockIdx.x;
    int oh   = blockIdx.y;
    int b    = blockIdx.z;
    int ow   = wid >> 2;
    int lw   = wid & 3;

    // stage issuer: stage s -> chunk s (k = s/4, ic = s%4), slot s%3
    auto issue = [&](int s) {
        if (s < KK * NCHUNK) {
            int k  = s >> 2;
            int ic = s & 3;
            uint32_t base = sb + (s % NSTAGE) * SLOT_BYTES;
            const char* srcA = (const char*)(g_wA + (size_t)((k * 4 + ic) * 2 + oh) * 8192);
            const char* srcB = (const char*)(g_I + (size_t)(((b * 7 + k) * 4 + ic) * NLT + lt) * 8192);
            #pragma unroll
            for (int q = 0; q < 4; q++)
                cp16(base + q * 4096 + tid * 16, srcA + q * 4096 + tid * 16);
            #pragma unroll
            for (int q = 0; q < 4; q++)
                cp16(base + 16384 + q * 4096 + tid * 16, srcB + q * 4096 + tid * 16);
        }
        asm volatile("cp.async.commit_group;" ::: "memory");
    };

    float c[4][4][4];
    #pragma unroll
    for (int ot = 0; ot < 4; ot++)
        #pragma unroll
        for (int nt = 0; nt < 4; nt++)
            #pragma unroll
            for (int r = 0; r < 4; r++) c[ot][nt][r] = 0.f;

    issue(0);
    issue(1);

    for (int cc = 0; cc < KK * NCHUNK; cc++) {
        asm volatile("cp.async.wait_group 1;" ::: "memory");   // stage cc ready
        __syncthreads();                                       // + slot (cc-1)%3 free
        issue(cc + 2);

        uint32_t aB = sb + (cc % NSTAGE) * SLOT_BYTES;
        uint32_t bB = aB + 16384;

        #pragma unroll
        for (int ks = 0; ks < 4; ks++) {
            uint32_t bf[4][2];
            #pragma unroll
            for (int np = 0; np < 2; np++) {
                int row = lw * 32 + np * 16 + ((lane >> 4) << 3) + (lane & 7);
                uint32_t off = SWZ128((uint32_t)(row * 128 + ks * 32 + ((lane >> 3) & 1) * 16));
                uint32_t r[4];
                ldsm4(r, bB + off);
                bf[np * 2][0]     = r[0]; bf[np * 2][1]     = r[1];
                bf[np * 2 + 1][0] = r[2]; bf[np * 2 + 1][1] = r[3];
            }
            #pragma unroll
            for (int ot = 0; ot < 4; ot++) {
                int row = ow * 64 + ot * 16 + (lane & 15);
                uint32_t off = SWZ128((uint32_t)(row * 128 + ks * 32 + (lane >> 4) * 16));
                uint32_t ah[4];
                ldsm4(ah, aB + off);
                #pragma unroll
                for (int nt = 0; nt < 4; nt++)
                    mma16816(c[ot][nt], ah, bf[nt]);
            }
        }
        __syncthreads();   // all warps done with slot before next refill cycle
    }

    // ---- epilogue: bias + store ----
    int og0 = oh * 128 + ow * 64;
    int l0  = lt * NT;
    #pragma unroll
    for (int ot = 0; ot < 4; ot++) {
        #pragma unroll
        for (int r2 = 0; r2 < 2; r2++) {
            int o = og0 + ot * 16 + (lane >> 2) + r2 * 8;
            float bj = bias[o];
            float* orow = out + ((size_t)(b * COUT + o)) * LEN + l0;
            #pragma unroll
            for (int nt = 0; nt < 4; nt++) {
                int lc = lw * 32 + nt * 8 + (lane & 3) * 2;
                *(float2*)(orow + lc) =
                    make_float2(c[ot][nt][r2 * 2] + bj, c[ot][nt][r2 * 2 + 1] + bj);
            }
        }
    }
}

// ---------------- launch ----------------
extern "C" void kernel_launch(void* const* d_in, const int* in_sizes, int n_in,
                              void* d_out, int out_size)
{
    const float* x        = (const float*)d_in[0];
    const float* weight   = (const float*)d_in[1];
    const float* bias     = (const float*)d_in[2];
    const float* offset_w = (const float*)d_in[3];
    const float* offset_b = (const float*)d_in[4];
    float* out = (float*)d_out;

    const int smem_prep = 256 * PCOLS * 4 + 7 * 256 * 8 * 4
                        + 7 * 128 * 8 + 7 * 128 * 2;           // 226048
    const int smem_main = NSTAGE * SLOT_BYTES;                 // 98304

    cudaFuncSetAttribute(prep_kernel, cudaFuncAttributeMaxDynamicSharedMemorySize, smem_prep);
    cudaFuncSetAttribute(main_kernel, cudaFuncAttributeMaxDynamicSharedMemorySize, smem_main);

    wprep_kernel<<<(KK * NCHUNK * 2 * 8192 + 255) / 256, 256>>>(weight);
    prep_kernel<<<dim3(NLT, BATCH), 512, smem_prep>>>(x, offset_w, offset_b);
    main_kernel<<<dim3(NLT, 2, BATCH), 256, smem_main>>>(bias, out);
}